// round 1
// baseline (speedup 1.0000x reference)
#include <cuda_runtime.h>
#include <math.h>

// Problem constants
#define BB   8
#define CC   512
#define HH   14
#define WW   14
#define HS   1024
#define KP   144      // 12x12 valid centers
#define NO   9        // offsets
#define HW   196      // HH*WW

// Scratch (device globals — no allocation allowed)
__device__ float g_wt1[CC * HS];            // w1 transposed: [c][h]
__device__ float g_wt2[CC * HS];            // w2 transposed: [c][h]
__device__ float g_cp [BB * KP * HS];       // center_proj  [b][k][h]
__device__ float g_sp [NO * BB * KP * HS];  // side_proj    [o][b][k][h]

// ---------------------------------------------------------------------------
// Transpose w1/w2 (HS x C, row-major) -> (C x HS) for coalesced B-tile loads
// grid (C/32, HS/32, 2), block (32, 8)
// ---------------------------------------------------------------------------
__global__ void transpose_w(const float* __restrict__ w1,
                            const float* __restrict__ w2) {
    __shared__ float tile[32][33];
    const float* src = blockIdx.z ? w2 : w1;
    float*       dst = blockIdx.z ? g_wt2 : g_wt1;
    int c0 = blockIdx.x * 32;
    int h0 = blockIdx.y * 32;
    for (int i = threadIdx.y; i < 32; i += 8)
        tile[i][threadIdx.x] = src[(h0 + i) * CC + c0 + threadIdx.x];
    __syncthreads();
    for (int i = threadIdx.y; i < 32; i += 8)
        dst[(c0 + i) * HS + h0 + threadIdx.x] = tile[threadIdx.x][i];
}

// ---------------------------------------------------------------------------
// Projection GEMM: rows = (o, b, k), o in [0,9]; o==9 means center (w1/b1).
// out[row][h] = sum_c x[b, c, y+dy, x+dx] * W[h][c] + bias[h]
// Total rows = 10*8*144 = 11520. Block = 64 rows x 64 h, K-tile 16.
// 1152 rows per o-segment; 1152 % 64 == 0 -> o constant per block.
// grid (HS/64=16, 11520/64=180), block 256
// ---------------------------------------------------------------------------
__global__ void proj_kernel(const float* __restrict__ x,
                            const float* __restrict__ b1,
                            const float* __restrict__ b2) {
    __shared__ float As[16][64];
    __shared__ float Bs[16][64];
    __shared__ int   rowbase[64];
    __shared__ float biasv[64];

    const int tid = threadIdx.x;
    const int h0  = blockIdx.x * 64;
    const int r0  = blockIdx.y * 64;

    const int o = r0 / (BB * KP);                 // 0..9, constant per block
    const float* wt   = (o == NO) ? g_wt1 : g_wt2;
    const float* bias = (o == NO) ? b1 : b2;
    float* outsec = (o == NO) ? g_cp : (g_sp + (size_t)o * BB * KP * HS);
    const int rem0 = r0 - o * (BB * KP);          // row offset within o-segment

    const int dy = (o == NO) ? 0 : (o / 3 - 1);
    const int dx = (o == NO) ? 0 : (o % 3 - 1);

    if (tid < 64) {
        int rem = rem0 + tid;
        int b = rem / KP;
        int k = rem - b * KP;
        int yy = 1 + k / 12 + dy;
        int xx = 1 + k % 12 + dx;
        rowbase[tid] = b * CC * HW + yy * WW + xx;   // c stride = HW
        biasv[tid]   = bias[h0 + tid];
    }
    __syncthreads();

    const int lr = tid & 63;      // row (A) / h (B) lane — coalesced
    const int lc = tid >> 6;      // 0..3
    const int ty = tid >> 4;      // 0..15
    const int tx = tid & 15;      // 0..15

    float acc[4][4] = {};

    for (int c0 = 0; c0 < CC; c0 += 16) {
        #pragma unroll
        for (int t = 0; t < 4; t++) {
            int cc = lc + 4 * t;
            As[cc][lr] = x[rowbase[lr] + (c0 + cc) * HW];
            Bs[cc][lr] = wt[(size_t)(c0 + cc) * HS + h0 + lr];
        }
        __syncthreads();
        #pragma unroll
        for (int kk = 0; kk < 16; kk++) {
            float a[4], bfr[4];
            #pragma unroll
            for (int m = 0; m < 4; m++) a[m]   = As[kk][ty * 4 + m];
            #pragma unroll
            for (int n = 0; n < 4; n++) bfr[n] = Bs[kk][tx * 4 + n];
            #pragma unroll
            for (int m = 0; m < 4; m++)
                #pragma unroll
                for (int n = 0; n < 4; n++)
                    acc[m][n] = fmaf(a[m], bfr[n], acc[m][n]);
        }
        __syncthreads();
    }

    #pragma unroll
    for (int m = 0; m < 4; m++) {
        int rem = rem0 + ty * 4 + m;
        float* op = outsec + (size_t)rem * HS + h0 + tx * 4;
        #pragma unroll
        for (int n = 0; n < 4; n++)
            op[n] = acc[m][n] + biasv[tx * 4 + n];
    }
}

// ---------------------------------------------------------------------------
// cofe GEMM: for pair (b,o): C[i][j] = sum_k cp[b][k][i] * sp[o][b][k][j]
// K=144 inner, 1024x1024 output per pair, written straight into d_out.
// grid (16, 16, 72), block 256; 64x64 tile, K-tile 16.
// ---------------------------------------------------------------------------
__global__ void cofe_kernel(float* __restrict__ out) {
    __shared__ float As[16][64];
    __shared__ float Bs[16][64];

    const int tid = threadIdx.x;
    const int j0  = blockIdx.x * 64;
    const int i0  = blockIdx.y * 64;
    const int p   = blockIdx.z;
    const int b   = p / NO;
    const int o   = p - b * NO;

    const float* A  = g_cp + (size_t)b * KP * HS;
    const float* Bm = g_sp + ((size_t)o * BB + b) * KP * HS;

    const int lr = tid & 63;
    const int lc = tid >> 6;
    const int ty = tid >> 4;
    const int tx = tid & 15;

    float acc[4][4] = {};

    for (int k0 = 0; k0 < KP; k0 += 16) {
        #pragma unroll
        for (int t = 0; t < 4; t++) {
            int kk = lc + 4 * t;
            As[kk][lr] = A [(size_t)(k0 + kk) * HS + i0 + lr];
            Bs[kk][lr] = Bm[(size_t)(k0 + kk) * HS + j0 + lr];
        }
        __syncthreads();
        #pragma unroll
        for (int kk = 0; kk < 16; kk++) {
            float a[4], bfr[4];
            #pragma unroll
            for (int m = 0; m < 4; m++) a[m]   = As[kk][ty * 4 + m];
            #pragma unroll
            for (int n = 0; n < 4; n++) bfr[n] = Bs[kk][tx * 4 + n];
            #pragma unroll
            for (int m = 0; m < 4; m++)
                #pragma unroll
                for (int n = 0; n < 4; n++)
                    acc[m][n] = fmaf(a[m], bfr[n], acc[m][n]);
        }
        __syncthreads();
    }

    // out layout: [b][o][i][j]
    #pragma unroll
    for (int m = 0; m < 4; m++) {
        size_t base = (((size_t)(b * NO + o) * HS) + (i0 + ty * 4 + m)) * HS + j0 + tx * 4;
        float4 v = make_float4(acc[m][0], acc[m][1], acc[m][2], acc[m][3]);
        *reinterpret_cast<float4*>(out + base) = v;
    }
}

// ---------------------------------------------------------------------------
// Row-normalize in place: one block per (b,o,i) row of 1024 floats.
// grid 8*9*1024 = 73728, block 256 (float4 per thread).
// ---------------------------------------------------------------------------
__global__ void norm_kernel(float* __restrict__ out) {
    __shared__ float ws[8];
    __shared__ float sc;

    const size_t row = blockIdx.x;
    float4* p = reinterpret_cast<float4*>(out + row * HS);
    float4 v = p[threadIdx.x];

    float s = v.x * v.x + v.y * v.y + v.z * v.z + v.w * v.w;
    #pragma unroll
    for (int off = 16; off > 0; off >>= 1)
        s += __shfl_xor_sync(0xffffffffu, s, off);
    if ((threadIdx.x & 31) == 0) ws[threadIdx.x >> 5] = s;
    __syncthreads();
    if (threadIdx.x == 0) {
        float t = 0.f;
        #pragma unroll
        for (int i = 0; i < 8; i++) t += ws[i];
        float nrm = sqrtf(t);
        sc = 1.0f / fmaxf(nrm, 1e-12f);
    }
    __syncthreads();
    float scale = sc;
    v.x *= scale; v.y *= scale; v.z *= scale; v.w *= scale;
    p[threadIdx.x] = v;
}

// ---------------------------------------------------------------------------
extern "C" void kernel_launch(void* const* d_in, const int* in_sizes, int n_in,
                              void* d_out, int out_size) {
    const float* x  = (const float*)d_in[0];
    const float* w1 = (const float*)d_in[1];
    const float* b1 = (const float*)d_in[2];
    const float* w2 = (const float*)d_in[3];
    const float* b2 = (const float*)d_in[4];
    float* out = (float*)d_out;

    transpose_w<<<dim3(CC / 32, HS / 32, 2), dim3(32, 8)>>>(w1, w2);
    proj_kernel<<<dim3(HS / 64, (10 * BB * KP) / 64), 256>>>(x, b1, b2);
    cofe_kernel<<<dim3(HS / 64, HS / 64, BB * NO), 256>>>(out);
    norm_kernel<<<BB * NO * HS, 256>>>(out);
}

// round 4
// speedup vs baseline: 2.0855x; 2.0855x over previous
#include <cuda_runtime.h>
#include <cuda_bf16.h>
#include <math.h>
#include <stdint.h>

#define BB 8
#define CC 512
#define HS 1024
#define KP 144
#define NO 9
#define HW 196
#define K3P 448          // 3*144 padded to 448 (mult of 32); pad stays zero

// ---------------- scratch (device globals; zero-initialized) ---------------
__device__ __align__(16) __nv_bfloat16 g_x3 [BB * HW * 1536];          // [(b,hw)][1536] = [Xh,Xh,Xl]
__device__ __align__(16) __nv_bfloat16 g_w13[HS * 1536];               // [h][1536]      = [Wh,Wl,Wh]
__device__ __align__(16) __nv_bfloat16 g_w23[HS * 1536];
__device__ __align__(16) __nv_bfloat16 g_cp3[BB * K3P * HS];           // [b][k3][i]     = [h,h,l]
__device__ __align__(16) __nv_bfloat16 g_sp3[NO * BB * K3P * HS];      // [o*8+b][k3][j] = [h,l,h]

// ---------------- asm helpers ----------------------------------------------
__device__ __forceinline__ uint32_t smem_u32(const void* p) {
    uint32_t a;
    asm("{ .reg .u64 t; cvta.to.shared.u64 t, %1; cvt.u32.u64 %0, t; }" : "=r"(a) : "l"(p));
    return a;
}
__device__ __forceinline__ void cp16(uint32_t s, const void* g) {
    asm volatile("cp.async.cg.shared.global [%0], [%1], 16;" :: "r"(s), "l"(g));
}
__device__ __forceinline__ void cpcommit() {
    asm volatile("cp.async.commit_group;" ::: "memory");
}
__device__ __forceinline__ void cpwait0() { asm volatile("cp.async.wait_group 0;" ::: "memory"); }
__device__ __forceinline__ void cpwait1() { asm volatile("cp.async.wait_group 1;" ::: "memory"); }

__device__ __forceinline__ void ldsm4(uint32_t* r, uint32_t a) {
    asm volatile("ldmatrix.sync.aligned.m8n8.x4.shared.b16 {%0,%1,%2,%3}, [%4];"
                 : "=r"(r[0]), "=r"(r[1]), "=r"(r[2]), "=r"(r[3]) : "r"(a));
}
__device__ __forceinline__ void ldsm4t(uint32_t* r, uint32_t a) {
    asm volatile("ldmatrix.sync.aligned.m8n8.x4.trans.shared.b16 {%0,%1,%2,%3}, [%4];"
                 : "=r"(r[0]), "=r"(r[1]), "=r"(r[2]), "=r"(r[3]) : "r"(a));
}
__device__ __forceinline__ void mma16816(float* c, const uint32_t* a, const uint32_t* b) {
    asm volatile(
        "mma.sync.aligned.m16n8k16.row.col.f32.bf16.bf16.f32 "
        "{%0,%1,%2,%3},{%4,%5,%6,%7},{%8,%9},{%0,%1,%2,%3};"
        : "+f"(c[0]), "+f"(c[1]), "+f"(c[2]), "+f"(c[3])
        : "r"(a[0]), "r"(a[1]), "r"(a[2]), "r"(a[3]), "r"(b[0]), "r"(b[1]));
}

// ---------------- convert kernels ------------------------------------------
__global__ void conv_w3(const float* __restrict__ w1, const float* __restrict__ w2) {
    int i = blockIdx.x * 256 + threadIdx.x;            // i over HS*CC
    const float* s = blockIdx.y ? w2 : w1;
    __nv_bfloat16* d = blockIdx.y ? g_w23 : g_w13;
    int h = i >> 9, c = i & 511;
    float v = s[i];
    __nv_bfloat16 hv = __float2bfloat16(v);
    __nv_bfloat16 lv = __float2bfloat16(v - __bfloat162float(hv));
    int base = h * 1536 + c;
    d[base] = hv; d[base + 512] = lv; d[base + 1024] = hv;   // [Wh,Wl,Wh]
}

__global__ void conv_x3(const float* __restrict__ x) {
    __shared__ float t[32][33];
    int b = blockIdx.z, hw0 = blockIdx.y * 32, c0 = blockIdx.x * 32;
    for (int i = threadIdx.y; i < 32; i += 8) {
        int hw = hw0 + threadIdx.x;
        t[i][threadIdx.x] = (hw < HW) ? x[((size_t)b * CC + c0 + i) * HW + hw] : 0.f;
    }
    __syncthreads();
    for (int i = threadIdx.y; i < 32; i += 8) {
        int hw = hw0 + i, c = c0 + threadIdx.x;
        if (hw < HW) {
            float v = t[threadIdx.x][i];
            __nv_bfloat16 hv = __float2bfloat16(v);
            __nv_bfloat16 lv = __float2bfloat16(v - __bfloat162float(hv));
            size_t base = ((size_t)b * HW + hw) * 1536 + c;
            g_x3[base] = hv; g_x3[base + 512] = hv; g_x3[base + 1024] = lv; // [Xh,Xh,Xl]
        }
    }
}

// ---------------- projection GEMM ------------------------------------------
// D[row][h] = sum_k' X3[row][k'] * W3[h][k'] ; M=rows(128/CTA), N=h(128), K'=1536
// smem: A [128][40] bf16 x2buf @0,10240 ; B [128][40] x2buf @20480,30720
// epilogue stage: float [64][132] @0 (reuse)
#define PROJ_SMEM 40960
__global__ void __launch_bounds__(256, 2) proj_kernel(const float* __restrict__ b1,
                                                      const float* __restrict__ b2) {
    extern __shared__ char smraw[];
    __shared__ int soff[128];
    __shared__ int doff[128];
    const uint32_t sb = smem_u32(smraw);
    const int tid = threadIdx.x, wid = tid >> 5, l = tid & 31;

    const int h0 = blockIdx.x * 128;
    const int r0 = blockIdx.y * 128;
    const int o = r0 / (BB * KP);
    const int rem0 = r0 - o * (BB * KP);
    const int dy = (o == NO) ? 0 : (o / 3 - 1);
    const int dx = (o == NO) ? 0 : (o % 3 - 1);

    if (tid < 128) {
        int rr = rem0 + tid;
        int b = rr / KP, k = rr - b * KP;
        int yy = 1 + k / 12 + dy, xx = 1 + k % 12 + dx;
        soff[tid] = (b * HW + yy * 14 + xx) * 1536;
        doff[tid] = (((o == NO) ? b : (o * BB + b)) * K3P + k) * HS;
    }
    const __nv_bfloat16* W = (o == NO) ? g_w13 : g_w23;
    const float* bias = (o == NO) ? b1 : b2;
    __nv_bfloat16* Dst = (o == NO) ? g_cp3 : g_sp3;
    __syncthreads();

    const uint32_t Ab[2] = {sb, sb + 10240};
    const uint32_t Bb[2] = {sb + 20480, sb + 30720};

    const int Wm = (wid >> 1) * 32, Wn = (wid & 1) * 64;
    const int aRow = (l & 15), aKb = (l >> 4) * 16;
    const int bN = (l & 7) + (l >> 4) * 8, bKb = ((l >> 3) & 1) * 16;

    float acc[2][8][4] = {};

    // prologue load it=0
    {
        #pragma unroll
        for (int i = 0; i < 2; i++) {
            int c = tid + i * 256, row = c >> 2, kc = c & 3;
            cp16(Ab[0] + row * 80 + kc * 16, g_x3 + soff[row] + kc * 8);
        }
        #pragma unroll
        for (int i = 0; i < 2; i++) {
            int c = tid + i * 256, row = c >> 2, kc = c & 3;
            cp16(Bb[0] + row * 80 + kc * 16, W + (size_t)(h0 + row) * 1536 + kc * 8);
        }
        cpcommit();
    }

    for (int it = 0; it < 48; ++it) {
        const int buf = it & 1;
        if (it + 1 < 48) {
            const int c0 = (it + 1) * 32, nb = buf ^ 1;
            #pragma unroll
            for (int i = 0; i < 2; i++) {
                int c = tid + i * 256, row = c >> 2, kc = c & 3;
                cp16(Ab[nb] + row * 80 + kc * 16, g_x3 + soff[row] + c0 + kc * 8);
            }
            #pragma unroll
            for (int i = 0; i < 2; i++) {
                int c = tid + i * 256, row = c >> 2, kc = c & 3;
                cp16(Bb[nb] + row * 80 + kc * 16, W + (size_t)(h0 + row) * 1536 + c0 + kc * 8);
            }
            cpcommit();
            cpwait1();
        } else {
            cpwait0();
        }
        __syncthreads();
        #pragma unroll
        for (int s = 0; s < 2; s++) {
            uint32_t a[2][4], bb[4][4];
            #pragma unroll
            for (int t = 0; t < 2; t++)
                ldsm4(a[t], Ab[buf] + (Wm + t * 16 + aRow) * 80 + s * 32 + aKb);
            #pragma unroll
            for (int p = 0; p < 4; p++)
                ldsm4(bb[p], Bb[buf] + (Wn + p * 16 + bN) * 80 + s * 32 + bKb);
            #pragma unroll
            for (int mt = 0; mt < 2; mt++)
                #pragma unroll
                for (int nt = 0; nt < 8; nt++)
                    mma16816(acc[mt][nt], a[mt], &bb[nt >> 1][(nt & 1) * 2]);
        }
        __syncthreads();
    }

    // epilogue: stage 64-row halves, add bias, split hi/lo, store triple
    float* stage = (float*)smraw;
    for (int half = 0; half < 2; ++half) {
        __syncthreads();
        if ((wid >> 2) == half) {
            int rbase = Wm - half * 64;
            #pragma unroll
            for (int mt = 0; mt < 2; mt++)
                #pragma unroll
                for (int nt = 0; nt < 8; nt++) {
                    int row = rbase + mt * 16 + (l >> 2);
                    int col = Wn + nt * 8 + 2 * (l & 3);
                    stage[row * 132 + col]           = acc[mt][nt][0];
                    stage[row * 132 + col + 1]       = acc[mt][nt][1];
                    stage[(row + 8) * 132 + col]     = acc[mt][nt][2];
                    stage[(row + 8) * 132 + col + 1] = acc[mt][nt][3];
                }
        }
        __syncthreads();
        for (int idx = tid; idx < 8192; idx += 256) {
            int m = idx >> 7, h = idx & 127;
            float v = stage[m * 132 + h] + bias[h0 + h];
            __nv_bfloat16 hv = __float2bfloat16(v);
            __nv_bfloat16 lv = __float2bfloat16(v - __bfloat162float(hv));
            int dbase = doff[half * 64 + m] + h0 + h;
            if (o == NO) {  // cp3 pattern [h,h,l]
                Dst[dbase] = hv; Dst[dbase + KP * HS] = hv; Dst[dbase + 2 * KP * HS] = lv;
            } else {        // sp3 pattern [h,l,h]
                Dst[dbase] = hv; Dst[dbase + KP * HS] = lv; Dst[dbase + 2 * KP * HS] = hv;
            }
        }
    }
}

// ---------------- cofe GEMM -------------------------------------------------
// C[i][j] = sum_k3 cp3[b][k3][i] * sp3[ob][k3][j] ; BM=256 i, BN=128 j, K'=448
// smem: A [32][264] bf16 x2 @0,16896 ; B [32][136] x2 @33792,42496
#define COFE_SMEM 51200
__global__ void __launch_bounds__(256, 1) cofe_kernel(float* __restrict__ out) {
    extern __shared__ char smraw[];
    const uint32_t sb = smem_u32(smraw);
    const int tid = threadIdx.x, wid = tid >> 5, l = tid & 31;
    const int j0 = blockIdx.x * 128, i0 = blockIdx.y * 256;
    const int p = blockIdx.z, b = p / NO, o = p - b * NO;

    const __nv_bfloat16* Ag = g_cp3 + (size_t)b * K3P * HS + i0;
    const __nv_bfloat16* Bg = g_sp3 + (size_t)(o * BB + b) * K3P * HS + j0;

    const uint32_t Ab[2] = {sb, sb + 16896};
    const uint32_t Bb[2] = {sb + 33792, sb + 42496};

    const int Wm = (wid >> 1) * 64, Wn = (wid & 1) * 64;
    const int aK = (l & 7) + (l >> 4) * 8, aI = ((l >> 3) & 1) * 8;
    const int bK = (l & 7) + ((l >> 3) & 1) * 8, bJ = (l >> 4) * 8;

    float acc[4][8][4] = {};

    // prologue
    {
        #pragma unroll
        for (int i = 0; i < 4; i++) {
            int c = tid + i * 256, k = c >> 5, ic = c & 31;
            cp16(Ab[0] + k * 528 + ic * 16, Ag + (size_t)k * HS + ic * 8);
        }
        #pragma unroll
        for (int i = 0; i < 2; i++) {
            int c = tid + i * 256, k = c >> 4, jc = c & 15;
            cp16(Bb[0] + k * 272 + jc * 16, Bg + (size_t)k * HS + jc * 8);
        }
        cpcommit();
    }

    for (int it = 0; it < 14; ++it) {
        const int buf = it & 1;
        if (it + 1 < 14) {
            const int k0 = (it + 1) * 32, nb = buf ^ 1;
            #pragma unroll
            for (int i = 0; i < 4; i++) {
                int c = tid + i * 256, k = c >> 5, ic = c & 31;
                cp16(Ab[nb] + k * 528 + ic * 16, Ag + (size_t)(k0 + k) * HS + ic * 8);
            }
            #pragma unroll
            for (int i = 0; i < 2; i++) {
                int c = tid + i * 256, k = c >> 4, jc = c & 15;
                cp16(Bb[nb] + k * 272 + jc * 16, Bg + (size_t)(k0 + k) * HS + jc * 8);
            }
            cpcommit();
            cpwait1();
        } else {
            cpwait0();
        }
        __syncthreads();
        #pragma unroll
        for (int s = 0; s < 2; s++) {
            uint32_t a[4][4], bb[4][4];
            #pragma unroll
            for (int t = 0; t < 4; t++)
                ldsm4t(a[t], Ab[buf] + (s * 16 + aK) * 528 + (Wm + t * 16 + aI) * 2);
            #pragma unroll
            for (int q = 0; q < 4; q++)
                ldsm4t(bb[q], Bb[buf] + (s * 16 + bK) * 272 + (Wn + q * 16 + bJ) * 2);
            #pragma unroll
            for (int mt = 0; mt < 4; mt++)
                #pragma unroll
                for (int nt = 0; nt < 8; nt++)
                    mma16816(acc[mt][nt], a[mt], &bb[nt >> 1][(nt & 1) * 2]);
        }
        __syncthreads();
    }

    float* outp = out + (size_t)p * HS * HS;
    #pragma unroll
    for (int mt = 0; mt < 4; mt++) {
        int gi = i0 + Wm + mt * 16 + (l >> 2);
        #pragma unroll
        for (int nt = 0; nt < 8; nt++) {
            int gj = j0 + Wn + nt * 8 + 2 * (l & 3);
            float2 v01 = make_float2(acc[mt][nt][0], acc[mt][nt][1]);
            float2 v23 = make_float2(acc[mt][nt][2], acc[mt][nt][3]);
            *reinterpret_cast<float2*>(outp + (size_t)gi * HS + gj) = v01;
            *reinterpret_cast<float2*>(outp + (size_t)(gi + 8) * HS + gj) = v23;
        }
    }
}

// ---------------- row normalize --------------------------------------------
__global__ void norm_kernel(float* __restrict__ out) {
    __shared__ float ws[8];
    __shared__ float sc;
    const size_t row = blockIdx.x;
    float4* p = reinterpret_cast<float4*>(out + row * HS);
    float4 v = p[threadIdx.x];
    float s = v.x * v.x + v.y * v.y + v.z * v.z + v.w * v.w;
    #pragma unroll
    for (int off = 16; off > 0; off >>= 1)
        s += __shfl_xor_sync(0xffffffffu, s, off);
    if ((threadIdx.x & 31) == 0) ws[threadIdx.x >> 5] = s;
    __syncthreads();
    if (threadIdx.x == 0) {
        float t = 0.f;
        #pragma unroll
        for (int i = 0; i < 8; i++) t += ws[i];
        sc = 1.0f / fmaxf(sqrtf(t), 1e-12f);
    }
    __syncthreads();
    float scale = sc;
    v.x *= scale; v.y *= scale; v.z *= scale; v.w *= scale;
    p[threadIdx.x] = v;
}

// ---------------------------------------------------------------------------
extern "C" void kernel_launch(void* const* d_in, const int* in_sizes, int n_in,
                              void* d_out, int out_size) {
    const float* x  = (const float*)d_in[0];
    const float* w1 = (const float*)d_in[1];
    const float* b1 = (const float*)d_in[2];
    const float* w2 = (const float*)d_in[3];
    const float* b2 = (const float*)d_in[4];
    float* out = (float*)d_out;

    cudaFuncSetAttribute(proj_kernel, cudaFuncAttributeMaxDynamicSharedMemorySize, PROJ_SMEM);
    cudaFuncSetAttribute(cofe_kernel, cudaFuncAttributeMaxDynamicSharedMemorySize, COFE_SMEM);

    conv_w3<<<dim3((HS * CC) / 256, 2), 256>>>(w1, w2);
    conv_x3<<<dim3(CC / 32, (HW + 31) / 32, BB), dim3(32, 8)>>>(x);
    proj_kernel<<<dim3(HS / 128, (10 * BB * KP) / 128), 256, PROJ_SMEM>>>(b1, b2);
    cofe_kernel<<<dim3(HS / 128, HS / 256, BB * NO), 256, COFE_SMEM>>>(out);
    norm_kernel<<<BB * NO * HS, 256>>>(out);
}